// round 5
// baseline (speedup 1.0000x reference)
#include <cuda_runtime.h>
#include <cuda_bf16.h>
#include <math.h>
#include <stdint.h>

#define BB   8
#define NPTS 8192
#define TT   2048
#define CW   1024
#define DW   256
#define NBLK 5
#define M_ENC (BB*NPTS)   /* 65536 */
#define M_DEC (BB*TT)     /* 16384 */

// ---------------- scratch (device globals; no allocation allowed) ----------
__device__ __nv_bfloat16 g_w2hi[(size_t)CW * CW];   // [n][k] transposed
__device__ __nv_bfloat16 g_w2lo[(size_t)CW * CW];
__device__ __nv_bfloat16 g_wdhi[10 * DW * DW];      // decoder weights [layer][n][k]
__device__ __nv_bfloat16 g_wdlo[10 * DW * DW];
__device__ int           g_sidx[M_ENC];
__device__ int           g_nv[BB];
__device__ int           g_cnt[BB];
__device__ float         g_p99[BB];
__device__ float         g_c[BB * CW];
__device__ float         g_net[M_DEC * DW];
__device__ float         g_t1[M_DEC * DW];
__device__ float         g_gamma[11 * BB * DW];
__device__ float         g_beta[11 * BB * DW];
__device__ float         g_psum[256 * DW];
__device__ float         g_psq[256 * DW];
__device__ float         g_mean[DW];
__device__ float         g_rstd[DW];

// ---------------- PTX helpers (all baseline sm_80+ features) ---------------
__device__ __forceinline__ uint32_t smem_u32(const void* p) {
    uint32_t a;
    asm("{ .reg .u64 t; cvta.to.shared.u64 t, %1; cvt.u32.u64 %0, t; }" : "=r"(a) : "l"(p));
    return a;
}
__device__ __forceinline__ void cp16(uint32_t dst, const void* src) {
    asm volatile("cp.async.cg.shared.global [%0], [%1], 16;"
                 :: "r"(dst), "l"(__cvta_generic_to_global(src)) : "memory");
}
#define CP_COMMIT() asm volatile("cp.async.commit_group;" ::: "memory")
template <int N>
__device__ __forceinline__ void cp_wait() {
    asm volatile("cp.async.wait_group %0;" :: "n"(N) : "memory");
}
__device__ __forceinline__ void ldsm4(uint32_t (&r)[4], uint32_t addr) {
    asm volatile("ldmatrix.sync.aligned.m8n8.x4.shared.b16 {%0,%1,%2,%3}, [%4];"
                 : "=r"(r[0]), "=r"(r[1]), "=r"(r[2]), "=r"(r[3]) : "r"(addr));
}
__device__ __forceinline__ void mma16816(float (&d)[4], const uint32_t (&a)[4],
                                         uint32_t b0, uint32_t b1) {
    asm volatile("mma.sync.aligned.m16n8k16.row.col.f32.bf16.bf16.f32 "
                 "{%0,%1,%2,%3}, {%4,%5,%6,%7}, {%8,%9}, {%0,%1,%2,%3};"
                 : "+f"(d[0]), "+f"(d[1]), "+f"(d[2]), "+f"(d[3])
                 : "r"(a[0]), "r"(a[1]), "r"(a[2]), "r"(a[3]), "r"(b0), "r"(b1));
}

// ---------------- small reduce helper --------------------------------------
__device__ __forceinline__ int blockReduceSumI(int v, int* sred) {
    for (int o = 16; o > 0; o >>= 1) v += __shfl_down_sync(0xffffffffu, v, o);
    int w = threadIdx.x >> 5;
    if ((threadIdx.x & 31) == 0) sred[w] = v;
    __syncthreads();
    if (threadIdx.x < 32) {
        int t = (threadIdx.x < (int)(blockDim.x >> 5)) ? sred[threadIdx.x] : 0;
        for (int o = 16; o > 0; o >>= 1) t += __shfl_down_sync(0xffffffffu, t, o);
        if (threadIdx.x == 0) sred[0] = t;
    }
    __syncthreads();
    int r = sred[0];
    __syncthreads();
    return r;
}

// ---------------- kernel: zero pooled code + counters ----------------------
__global__ void zero_kernel() {
    g_c[blockIdx.x * 1024 + threadIdx.x] = 0.0f;
    if (blockIdx.x == 0 && threadIdx.x < BB) g_cnt[threadIdx.x] = 0;
}

// ---------------- kernel: per-batch 99th percentile (exact kthvalue) -------
__global__ __launch_bounds__(1024) void p99_kernel(const float* __restrict__ pts) {
    __shared__ unsigned s_bits[NPTS];
    __shared__ int sred[33];
    const int b = blockIdx.x, tid = threadIdx.x;
    const float* p = pts + (size_t)b * NPTS * 3;
    int nv = 0;
    for (int i = tid; i < NPTS; i += 1024) {
        float x = p[3 * i], y = p[3 * i + 1], z = p[3 * i + 2];
        bool valid = x > -50.0f;
        float nr = valid ? sqrtf(x * x + y * y + z * z) : __int_as_float(0x7F800000);
        s_bits[i] = __float_as_uint(nr);
        nv += valid ? 1 : 0;
    }
    int total = blockReduceSumI(nv, sred);
    __shared__ int s_k;
    if (tid == 0) {
        s_k = 1 + (int)rintf(0.99f * (float)(total - 1));
        g_nv[b] = total;
    }
    __syncthreads();
    const int k = s_k;
    unsigned lo = 0u, hi = 0x7F800000u;
    while (lo < hi) {
        unsigned mid = (lo + hi) >> 1;
        int c = 0;
        for (int i = tid; i < NPTS; i += 1024) c += (s_bits[i] <= mid) ? 1 : 0;
        c = blockReduceSumI(c, sred);
        if (c >= k) hi = mid; else lo = mid + 1;
    }
    if (tid == 0) g_p99[b] = __uint_as_float(lo);
}

// ---------------- kernel: valid-point compaction ---------------------------
__global__ __launch_bounds__(1024) void compact_kernel(const float* __restrict__ pts) {
    int i = blockIdx.x * 1024 + threadIdx.x;
    if (pts[(size_t)i * 3] > -50.0f) {
        int b = i >> 13;
        int dst = atomicAdd(&g_cnt[b], 1);
        g_sidx[(b << 13) + dst] = i;
    }
}

// ---------------- kernel: W2 transpose + bf16 hi/lo split ------------------
__global__ __launch_bounds__(256) void w2conv_kernel(const float* __restrict__ W2) {
    __shared__ float t[32][33];
    const int bx = blockIdx.x, by = blockIdx.y;
    const int x = threadIdx.x & 31, y0 = threadIdx.x >> 5;
#pragma unroll
    for (int dy = 0; dy < 32; dy += 8)
        t[y0 + dy][x] = W2[(size_t)(by * 32 + y0 + dy) * CW + bx * 32 + x];
    __syncthreads();
#pragma unroll
    for (int dy = 0; dy < 32; dy += 8) {
        float v = t[x][y0 + dy];
        __nv_bfloat16 hi = __float2bfloat16(v);
        __nv_bfloat16 lo = __float2bfloat16(v - __bfloat162float(hi));
        size_t o = (size_t)(bx * 32 + y0 + dy) * CW + by * 32 + x;
        g_w2hi[o] = hi;
        g_w2lo[o] = lo;
    }
}

// ---------------- kernel: decoder weights transpose + split ----------------
__global__ __launch_bounds__(256) void wdec_kernel(const float* __restrict__ W0,
                                                   const float* __restrict__ W1) {
    __shared__ float t[32][33];
    const int bx = blockIdx.x, by = blockIdx.y, z = blockIdx.z;
    const float* src = ((z & 1) ? W1 : W0) + (size_t)(z >> 1) * DW * DW;
    const int x = threadIdx.x & 31, y0 = threadIdx.x >> 5;
#pragma unroll
    for (int dy = 0; dy < 32; dy += 8)
        t[y0 + dy][x] = src[(size_t)(by * 32 + y0 + dy) * DW + bx * 32 + x];
    __syncthreads();
#pragma unroll
    for (int dy = 0; dy < 32; dy += 8) {
        float v = t[x][y0 + dy];
        __nv_bfloat16 hi = __float2bfloat16(v);
        __nv_bfloat16 lo = __float2bfloat16(v - __bfloat162float(hi));
        size_t o = (size_t)z * DW * DW + (size_t)(bx * 32 + y0 + dy) * DW + by * 32 + x;
        g_wdhi[o] = hi;
        g_wdlo[o] = lo;
    }
}

// ---------------- kernel: fused enc1+enc2 mma GEMM + masked maxpool --------
// CTA tile 128M x 256N, K-stage 32. A tile computed in-kernel from x (6-dim).
// smem: B stages 3 x (Bhi 20480 + Blo 20480) | A bufs 2 x (Ahi 10240 + Alo 10240)
//       | W1 24576 | b1 4096 | x 3072
#define E2_BSTG   40960
#define E2_ABUF   122880
#define E2_W1     163840
#define E2_B1     188416
#define E2_X      192512
#define E2_SMEM   195584

__global__ __launch_bounds__(256, 1) void enc2_mma_kernel(const float* __restrict__ pts,
                                                          const float* __restrict__ rgb,
                                                          const float* __restrict__ W1g,
                                                          const float* __restrict__ b1g,
                                                          const float* __restrict__ b2) {
    extern __shared__ __align__(128) char sm[];
    __shared__ float sbias[256];
    const uint32_t smb = smem_u32(sm);
    const int tid = threadIdx.x;
    const int cb = blockIdx.x;          // 0..3  N-strip of 256
    const int rb = blockIdx.y;          // 0..511 M-tile of 128
    const int batch = rb >> 6;
    const int n_b = g_nv[batch];
    const int rib0 = (rb & 63) * 128;
    if (rib0 >= n_b) return;
    const int validRows = n_b - rib0;
    const int l = tid & 31, w = tid >> 5;
    const int warp_m = w >> 2, warp_n = w & 3;

    sbias[tid] = b2[cb * 256 + tid];

    // B cp.async mapping (8 chunks/thread/stage)
    const __nv_bfloat16* gsrc[8];
    uint32_t soff[8];
#pragma unroll
    for (int q = 0; q < 8; q++) {
        int ch = tid + q * 256;
        int plane = ch >> 10, idx = ch & 1023;
        int row = idx >> 2, c = idx & 3;
        gsrc[q] = (plane ? g_w2lo : g_w2hi) + (size_t)(cb * 256 + row) * CW + c * 8;
        soff[q] = plane * 20480 + row * 80 + c * 16;
    }
#define E2_ISSUE(it) do { \
        uint32_t sb_ = smb + ((it) % 3) * E2_BSTG; \
        _Pragma("unroll") \
        for (int q = 0; q < 8; q++) cp16(sb_ + soff[q], gsrc[q] + (it) * 32); \
        CP_COMMIT(); \
    } while (0)

    // prologue group0: W1 + b1 + B(0); group1: B(1)
#pragma unroll
    for (int q = 0; q < 6; q++) {
        int ch = tid + q * 256;
        cp16(smb + E2_W1 + ch * 16, W1g + ch * 4);
    }
    cp16(smb + E2_B1 + tid * 16, b1g + tid * 4);
    E2_ISSUE(0);
    E2_ISSUE(1);

    // x gather (plain loads)
    if (tid < 128) {
        int idx = rib0 + tid;
        if (idx >= n_b) idx = n_b - 1;
        int src = g_sidx[(batch << 13) + idx];
        float p99v = g_p99[batch];
        float* sx = (float*)(sm + E2_X) + tid * 6;
        sx[0] = pts[(size_t)src * 3 + 0] / p99v;
        sx[1] = pts[(size_t)src * 3 + 1] / p99v;
        sx[2] = pts[(size_t)src * 3 + 2] / p99v;
        sx[3] = rgb[(size_t)src * 3 + 0];
        sx[4] = rgb[(size_t)src * 3 + 1];
        sx[5] = rgb[(size_t)src * 3 + 2];
    }
    cp_wait<1>();                       // W1, b1, B(0) landed
    __syncthreads();                    // + x visible

    // --- compute A stage s (relu(x@W1+b1), hi/lo split) --------------------
    const int arow = tid >> 1, ahalf = tid & 1;
    float xr[6];
    {
        const float* sx = (const float*)(sm + E2_X) + arow * 6;
#pragma unroll
        for (int j = 0; j < 6; j++) xr[j] = sx[j];
    }
    const float* sW1 = (const float*)(sm + E2_W1);
    const float* sb1 = (const float*)(sm + E2_B1);
#define E2_COMPUTE_A(s) do { \
        int k0 = (s) * 32 + ahalf * 16; \
        uint32_t hi[8], lo[8]; \
        _Pragma("unroll") \
        for (int c2 = 0; c2 < 8; c2++) { \
            float z0 = sb1[k0 + 2 * c2], z1 = sb1[k0 + 2 * c2 + 1]; \
            _Pragma("unroll") \
            for (int j = 0; j < 6; j++) { \
                z0 += xr[j] * sW1[j * CW + k0 + 2 * c2]; \
                z1 += xr[j] * sW1[j * CW + k0 + 2 * c2 + 1]; \
            } \
            float v0 = fmaxf(z0, 0.f), v1 = fmaxf(z1, 0.f); \
            __nv_bfloat16 h0 = __float2bfloat16(v0), h1 = __float2bfloat16(v1); \
            __nv_bfloat16 l0 = __float2bfloat16(v0 - __bfloat162float(h0)); \
            __nv_bfloat16 l1 = __float2bfloat16(v1 - __bfloat162float(h1)); \
            hi[c2] = (uint32_t)*(uint16_t*)&h0 | ((uint32_t)*(uint16_t*)&h1 << 16); \
            lo[c2] = (uint32_t)*(uint16_t*)&l0 | ((uint32_t)*(uint16_t*)&l1 << 16); \
        } \
        char* dh = sm + E2_ABUF + ((s) & 1) * 20480 + arow * 80 + ahalf * 32; \
        ((uint4*)dh)[0] = make_uint4(hi[0], hi[1], hi[2], hi[3]); \
        ((uint4*)dh)[1] = make_uint4(hi[4], hi[5], hi[6], hi[7]); \
        char* dl = dh + 10240; \
        ((uint4*)dl)[0] = make_uint4(lo[0], lo[1], lo[2], lo[3]); \
        ((uint4*)dl)[1] = make_uint4(lo[4], lo[5], lo[6], lo[7]); \
    } while (0)

    E2_COMPUTE_A(0);

    const uint32_t a_lane = (uint32_t)(warp_m * 64 + (l & 15)) * 80 + ((l >> 4) & 1) * 16;
    const uint32_t b_lane = (uint32_t)(warp_n * 64 + ((l >> 4) & 1) * 8 + (l & 7)) * 80
                          + ((l >> 3) & 1) * 16;

    float acc[4][8][4];
#pragma unroll
    for (int m = 0; m < 4; m++)
#pragma unroll
        for (int n = 0; n < 8; n++)
#pragma unroll
            for (int j = 0; j < 4; j++) acc[m][n][j] = 0.0f;

    const int NIT = CW / 32;            // 32
#pragma unroll 1
    for (int it = 0; it < NIT; it++) {
        if (it + 1 < NIT) cp_wait<1>(); else cp_wait<0>();
        __syncthreads();                // B(it) visible; A(it) visible; safe to reuse bufs
        if (it + 2 < NIT) E2_ISSUE(it + 2);
        if (it + 1 < NIT) E2_COMPUTE_A(it + 1);

        const uint32_t ba = smb + E2_ABUF + (it & 1) * 20480;
        const uint32_t bb_ = smb + (it % 3) * E2_BSTG;
#pragma unroll
        for (int k16 = 0; k16 < 2; k16++) {
            const uint32_t kb = k16 * 32;
            uint32_t Ah[4][4], Bh[4][4];
#pragma unroll
            for (int m = 0; m < 4; m++)
                ldsm4(Ah[m], ba + a_lane + m * (16 * 80) + kb);
#pragma unroll
            for (int p = 0; p < 4; p++)
                ldsm4(Bh[p], bb_ + b_lane + p * (16 * 80) + kb);
#pragma unroll
            for (int m = 0; m < 4; m++)
#pragma unroll
                for (int p = 0; p < 4; p++) {
                    mma16816(acc[m][2 * p],     Ah[m], Bh[p][0], Bh[p][1]);
                    mma16816(acc[m][2 * p + 1], Ah[m], Bh[p][2], Bh[p][3]);
                }
            uint32_t Bl[4][4];
#pragma unroll
            for (int p = 0; p < 4; p++)
                ldsm4(Bl[p], bb_ + 20480 + b_lane + p * (16 * 80) + kb);
#pragma unroll
            for (int m = 0; m < 4; m++)
#pragma unroll
                for (int p = 0; p < 4; p++) {
                    mma16816(acc[m][2 * p],     Ah[m], Bl[p][0], Bl[p][1]);
                    mma16816(acc[m][2 * p + 1], Ah[m], Bl[p][2], Bl[p][3]);
                }
            uint32_t Al[4][4];
#pragma unroll
            for (int m = 0; m < 4; m++)
                ldsm4(Al[m], ba + 10240 + a_lane + m * (16 * 80) + kb);
#pragma unroll
            for (int m = 0; m < 4; m++)
#pragma unroll
                for (int p = 0; p < 4; p++) {
                    mma16816(acc[m][2 * p],     Al[m], Bh[p][0], Bh[p][1]);
                    mma16816(acc[m][2 * p + 1], Al[m], Bh[p][2], Bh[p][3]);
                }
        }
    }

    // --- epilogue: bias + relu + masked column max -> atomicMax ------------
    const int groupID = l >> 2, tig = l & 3;
    unsigned mA[4], mB[4];
#pragma unroll
    for (int m = 0; m < 4; m++) {
        mA[m] = (warp_m * 64 + m * 16 + groupID)     < validRows;
        mB[m] = (warp_m * 64 + m * 16 + groupID + 8) < validRows;
    }
    const float NEGINF = __int_as_float(0xFF800000);
#pragma unroll
    for (int nt = 0; nt < 8; nt++) {
#pragma unroll
        for (int p = 0; p < 2; p++) {
            float bias = sbias[warp_n * 64 + nt * 8 + tig * 2 + p];
            float cm = NEGINF;
#pragma unroll
            for (int m = 0; m < 4; m++) {
                if (mA[m]) cm = fmaxf(cm, fmaxf(acc[m][nt][p] + bias, 0.0f));
                if (mB[m]) cm = fmaxf(cm, fmaxf(acc[m][nt][2 + p] + bias, 0.0f));
            }
            cm = fmaxf(cm, __shfl_xor_sync(0xffffffffu, cm, 16));
            cm = fmaxf(cm, __shfl_xor_sync(0xffffffffu, cm, 8));
            cm = fmaxf(cm, __shfl_xor_sync(0xffffffffu, cm, 4));
            if (l < 4)
                atomicMax((int*)&g_c[batch * CW + cb * 256 + warp_n * 64 + nt * 8 + l * 2 + p],
                          __float_as_int(cm));
        }
    }
#undef E2_ISSUE
#undef E2_COMPUTE_A
}

// ---------------- kernel: all 22 CBN gamma/beta projections ----------------
__global__ __launch_bounds__(1024) void gb_kernel(
    const float* __restrict__ Wg0, const float* __restrict__ bg0,
    const float* __restrict__ Wb0, const float* __restrict__ bb0,
    const float* __restrict__ Wg1, const float* __restrict__ bg1,
    const float* __restrict__ Wb1, const float* __restrict__ bb1,
    const float* __restrict__ bnWg, const float* __restrict__ bnbg,
    const float* __restrict__ bnWb, const float* __restrict__ bnbb) {
    __shared__ float sc[CW];
    __shared__ float rg[4][DW], rb[4][DW];
    const int b = blockIdx.x, id = blockIdx.y;
    const int tid = threadIdx.x;
    for (int i = tid; i < CW; i += 1024) sc[i] = g_c[b * CW + i];
    const float *Wg, *Wb, *bg, *bbp;
    if (id < 10) {
        int i = id >> 1;
        if (!(id & 1)) { Wg = Wg0 + (size_t)i * CW * DW; bg = bg0 + i * DW;
                         Wb = Wb0 + (size_t)i * CW * DW; bbp = bb0 + i * DW; }
        else           { Wg = Wg1 + (size_t)i * CW * DW; bg = bg1 + i * DW;
                         Wb = Wb1 + (size_t)i * CW * DW; bbp = bb1 + i * DW; }
    } else { Wg = bnWg; bg = bnbg; Wb = bnWb; bbp = bnbb; }
    __syncthreads();
    const int col = tid & 255, kc = tid >> 8;
    float sg = 0.f, sb = 0.f;
    for (int k = kc * 256; k < (kc + 1) * 256; k++) {
        float cv = sc[k];
        sg += cv * Wg[(size_t)k * DW + col];
        sb += cv * Wb[(size_t)k * DW + col];
    }
    rg[kc][col] = sg; rb[kc][col] = sb;
    __syncthreads();
    if (tid < 256) {
        float ga = bg[col], be = bbp[col];
#pragma unroll
        for (int t = 0; t < 4; t++) { ga += rg[t][col]; be += rb[t][col]; }
        g_gamma[(id * BB + b) * DW + col] = ga;
        g_beta [(id * BB + b) * DW + col] = be;
    }
}

// ---------------- kernel: fc_p (3 -> 256) + fused stats (256 slots) --------
__global__ __launch_bounds__(256) void fcp_kernel(const float* __restrict__ qc,
                                                  const float* __restrict__ W,
                                                  const float* __restrict__ bias) {
    __shared__ float sW[3 * DW];
    __shared__ float sx[64][3];
    const int tid = threadIdx.x;
    const int r0 = blockIdx.x * 64;
    const int b = r0 >> 11;
    for (int i = tid; i < 3 * DW; i += 256) sW[i] = W[i];
    if (tid < 192) {
        int r = tid / 3, cc = tid % 3;
        sx[r][cc] = qc[(size_t)(r0 + r) * 3 + cc] / g_p99[b];
    }
    __syncthreads();
    const int col = tid;
    const float bv = bias[col];
    float s = 0.f, q = 0.f;
    for (int r = 0; r < 64; r++) {
        float o = bv;
#pragma unroll
        for (int k = 0; k < 3; k++) o += sx[r][k] * sW[k * DW + col];
        g_net[(size_t)(r0 + r) * DW + col] = o;
        s += o; q += o * o;
    }
    g_psum[(size_t)blockIdx.x * DW + col] = s;
    g_psq [(size_t)blockIdx.x * DW + col] = q;
}

// ---------------- kernel: BN stats finalize (pre-head only) ----------------
__global__ __launch_bounds__(256) void stats_final_kernel() {
    const int col = threadIdx.x;
    float s = 0.f, q = 0.f;
#pragma unroll 8
    for (int t = 0; t < 256; t++) {
        s += g_psum[(size_t)t * DW + col];
        q += g_psq [(size_t)t * DW + col];
    }
    float mean = s * (1.0f / 16384.0f);
    float var = q * (1.0f / 16384.0f) - mean * mean;
    if (var < 0.f) var = 0.f;
    g_mean[col] = mean;
    g_rstd[col] = rsqrtf(var + 1e-5f);
}

// ---------------- kernel: decoder mma GEMM, fused stats+CBN+ReLU -----------
#define D_AF32  0
#define D_AHI   18432
#define D_ALO   28672
#define D_BHI   38912
#define D_BLO   59392
#define D_STAGE 79872
#define D_SMEM  (2 * D_STAGE)

template <int ADD>
__global__ __launch_bounds__(256, 1) void dec_mma_kernel(int xsel, int id, int layer,
                                                         const float* __restrict__ bias) {
    extern __shared__ __align__(128) char sm[];
    __shared__ float s_sc[DW], s_sh[DW], s_bias[DW];
    const uint32_t smb = smem_u32(sm);
    const int tid = threadIdx.x;
    const int rb = blockIdx.x;          // 0..127 M-tiles
    const int batch = rb >> 4;
    const int l = tid & 31, w = tid >> 5;
    const int warp_m = w >> 2, warp_n = w & 3;
    const float* X = xsel ? g_t1 : g_net;
    float* out = ADD ? g_net : g_t1;

    const float* asrc[4]; uint32_t aoff[4];
#pragma unroll
    for (int q = 0; q < 4; q++) {
        int ch = tid + q * 256;
        int row = ch >> 3, c = ch & 7;
        asrc[q] = X + (size_t)(rb * 128 + row) * DW + c * 4;
        aoff[q] = D_AF32 + row * 144 + c * 16;
    }
    const __nv_bfloat16* bsrc[8]; uint32_t boff[8];
#pragma unroll
    for (int q = 0; q < 8; q++) {
        int ch = tid + q * 256;
        int plane = ch >> 10, idx = ch & 1023;
        int row = idx >> 2, c = idx & 3;
        bsrc[q] = (plane ? g_wdlo : g_wdhi) + (size_t)layer * DW * DW + row * DW + c * 8;
        boff[q] = D_BHI + plane * 20480 + row * 80 + c * 16;
    }
#define D_ISSUE(it) do { \
        uint32_t sb_ = smb + ((it) & 1) * D_STAGE; \
        _Pragma("unroll") for (int q = 0; q < 4; q++) cp16(sb_ + aoff[q], asrc[q] + (it) * 32); \
        _Pragma("unroll") for (int q = 0; q < 8; q++) cp16(sb_ + boff[q], bsrc[q] + (it) * 32); \
        CP_COMMIT(); \
    } while (0)

    D_ISSUE(0);
    D_ISSUE(1);

    // fused BN stats (overlaps the cp.async above)
    {
        float s = 0.f, q = 0.f;
#pragma unroll 8
        for (int t = 0; t < 256; t++) {
            s += g_psum[(size_t)t * DW + tid];
            q += g_psq [(size_t)t * DW + tid];
        }
        float mean = s * (1.0f / 16384.0f);
        float var = q * (1.0f / 16384.0f) - mean * mean;
        if (var < 0.f) var = 0.f;
        float rstd = rsqrtf(var + 1e-5f);
        float sc = g_gamma[(id * BB + batch) * DW + tid] * rstd;
        s_sc[tid] = sc;
        s_sh[tid] = g_beta[(id * BB + batch) * DW + tid] - mean * sc;
        s_bias[tid] = bias[tid];
    }

    const uint32_t a_lane = (uint32_t)(warp_m * 64 + (l & 15)) * 80 + ((l >> 4) & 1) * 16;
    const uint32_t b_lane = (uint32_t)(warp_n * 64 + ((l >> 4) & 1) * 8 + (l & 7)) * 80
                          + ((l >> 3) & 1) * 16;

    float acc[4][8][4];
#pragma unroll
    for (int m = 0; m < 4; m++)
#pragma unroll
        for (int n = 0; n < 8; n++)
#pragma unroll
            for (int j = 0; j < 4; j++) acc[m][n][j] = 0.0f;

    const int cmr = tid >> 1, ckq = (tid & 1) * 16;
    const int NIT = DW / 32;            // 8
#pragma unroll 1
    for (int it = 0; it < NIT; it++) {
        if (it + 1 < NIT) cp_wait<1>(); else cp_wait<0>();
        __syncthreads();
        const int buf = it & 1;
        {
            const char* afp = sm + buf * D_STAGE + D_AF32 + cmr * 144 + ckq * 4;
            float4 f0 = *(const float4*)(afp);
            float4 f1 = *(const float4*)(afp + 16);
            float4 f2 = *(const float4*)(afp + 32);
            float4 f3 = *(const float4*)(afp + 48);
            float f[16] = {f0.x, f0.y, f0.z, f0.w, f1.x, f1.y, f1.z, f1.w,
                           f2.x, f2.y, f2.z, f2.w, f3.x, f3.y, f3.z, f3.w};
            uint32_t hi[8], lo[8];
#pragma unroll
            for (int j = 0; j < 8; j++) {
                int k0 = it * 32 + ckq + 2 * j;
                float va = fmaxf(fmaf(f[2 * j],     s_sc[k0],     s_sh[k0]),     0.f);
                float vb = fmaxf(fmaf(f[2 * j + 1], s_sc[k0 + 1], s_sh[k0 + 1]), 0.f);
                __nv_bfloat16 ha = __float2bfloat16(va), hb = __float2bfloat16(vb);
                __nv_bfloat16 la = __float2bfloat16(va - __bfloat162float(ha));
                __nv_bfloat16 lb = __float2bfloat16(vb - __bfloat162float(hb));
                hi[j] = (uint32_t)*(uint16_t*)&ha | ((uint32_t)*(uint16_t*)&hb << 16);
                lo[j] = (uint32_t)*(uint16_t*)&la | ((uint32_t)*(uint16_t*)&lb << 16);
            }
            char* dh = sm + buf * D_STAGE + D_AHI + cmr * 80 + ckq * 2;
            ((uint4*)dh)[0] = make_uint4(hi[0], hi[1], hi[2], hi[3]);
            ((uint4*)dh)[1] = make_uint4(hi[4], hi[5], hi[6], hi[7]);
            char* dl = sm + buf * D_STAGE + D_ALO + cmr * 80 + ckq * 2;
            ((uint4*)dl)[0] = make_uint4(lo[0], lo[1], lo[2], lo[3]);
            ((uint4*)dl)[1] = make_uint4(lo[4], lo[5], lo[6], lo[7]);
        }
        __syncthreads();
        const uint32_t bs = smb + buf * D_STAGE;
#pragma unroll
        for (int k16 = 0; k16 < 2; k16++) {
            const uint32_t kb = k16 * 32;
            uint32_t Ah[4][4], Bh[4][4];
#pragma unroll
            for (int m = 0; m < 4; m++)
                ldsm4(Ah[m], bs + D_AHI + a_lane + m * (16 * 80) + kb);
#pragma unroll
            for (int p = 0; p < 4; p++)
                ldsm4(Bh[p], bs + D_BHI + b_lane + p * (16 * 80) + kb);
#pragma unroll
            for (int m = 0; m < 4; m++)
#pragma unroll
                for (int p = 0; p < 4; p++) {
                    mma16816(acc[m][2 * p],     Ah[m], Bh[p][0], Bh[p][1]);
                    mma16816(acc[m][2 * p + 1], Ah[m], Bh[p][2], Bh[p][3]);
                }
            uint32_t Bl[4][4];
#pragma unroll
            for (int p = 0; p < 4; p++)
                ldsm4(Bl[p], bs + D_BLO + b_lane + p * (16 * 80) + kb);
#pragma unroll
            for (int m = 0; m < 4; m++)
#pragma unroll
                for (int p = 0; p < 4; p++) {
                    mma16816(acc[m][2 * p],     Ah[m], Bl[p][0], Bl[p][1]);
                    mma16816(acc[m][2 * p + 1], Ah[m], Bl[p][2], Bl[p][3]);
                }
            uint32_t Al[4][4];
#pragma unroll
            for (int m = 0; m < 4; m++)
                ldsm4(Al[m], bs + D_ALO + a_lane + m * (16 * 80) + kb);
#pragma unroll
            for (int m = 0; m < 4; m++)
#pragma unroll
                for (int p = 0; p < 4; p++) {
                    mma16816(acc[m][2 * p],     Al[m], Bh[p][0], Bh[p][1]);
                    mma16816(acc[m][2 * p + 1], Al[m], Bh[p][2], Bh[p][3]);
                }
        }
        __syncthreads();
        if (it + 2 < NIT) D_ISSUE(it + 2);
    }
#undef D_ISSUE

    // --- epilogue: bias (+residual), store, fused column stats -------------
    const int groupID = l >> 2, tig = l & 3;
    const int slot = rb * 2 + warp_m;
#pragma unroll
    for (int nt = 0; nt < 8; nt++) {
        const int colbase = warp_n * 64 + nt * 8 + tig * 2;
        const float bv0 = s_bias[colbase], bv1 = s_bias[colbase + 1];
        float s0 = 0.f, s1 = 0.f, q0 = 0.f, q1 = 0.f;
#pragma unroll
        for (int m = 0; m < 4; m++) {
            int r = rb * 128 + warp_m * 64 + m * 16 + groupID;
            float v00 = acc[m][nt][0] + bv0, v01 = acc[m][nt][1] + bv1;
            float v10 = acc[m][nt][2] + bv0, v11 = acc[m][nt][3] + bv1;
            if (ADD) {
                float2 o0 = *(const float2*)&g_net[(size_t)r * DW + colbase];
                float2 o1 = *(const float2*)&g_net[(size_t)(r + 8) * DW + colbase];
                v00 += o0.x; v01 += o0.y; v10 += o1.x; v11 += o1.y;
            }
            *(float2*)&out[(size_t)r * DW + colbase]       = make_float2(v00, v01);
            *(float2*)&out[(size_t)(r + 8) * DW + colbase] = make_float2(v10, v11);
            s0 += v00 + v10; s1 += v01 + v11;
            q0 += v00 * v00 + v10 * v10; q1 += v01 * v01 + v11 * v11;
        }
#pragma unroll
        for (int o = 16; o >= 4; o >>= 1) {
            s0 += __shfl_xor_sync(0xffffffffu, s0, o);
            s1 += __shfl_xor_sync(0xffffffffu, s1, o);
            q0 += __shfl_xor_sync(0xffffffffu, q0, o);
            q1 += __shfl_xor_sync(0xffffffffu, q1, o);
        }
        if (l < 4) {
            g_psum[(size_t)slot * DW + colbase]     = s0;
            g_psum[(size_t)slot * DW + colbase + 1] = s1;
            g_psq [(size_t)slot * DW + colbase]     = q0;
            g_psq [(size_t)slot * DW + colbase + 1] = q1;
        }
    }
}

// ---------------- kernel: final head (CBN+ReLU then 256 -> 1) --------------
__global__ __launch_bounds__(256) void head_kernel(const float* __restrict__ Wout,
                                                   const float* __restrict__ bout,
                                                   float* __restrict__ out) {
    __shared__ float s_sc[DW], s_sh[DW], s_w[DW];
    const int tid = threadIdx.x;
    const int r0 = blockIdx.x * 8;
    const int batch = r0 >> 11;
    if (tid < DW) {
        float sc = g_gamma[(10 * BB + batch) * DW + tid] * g_rstd[tid];
        s_sc[tid] = sc;
        s_sh[tid] = g_beta[(10 * BB + batch) * DW + tid] - g_mean[tid] * sc;
        s_w[tid] = Wout[tid];
    }
    __syncthreads();
    const int w = tid >> 5, l = tid & 31;
    const int row = r0 + w;
    float acc = 0.f;
#pragma unroll
    for (int k = l; k < DW; k += 32) {
        float v = fmaxf(s_sc[k] * g_net[(size_t)row * DW + k] + s_sh[k], 0.f);
        acc += v * s_w[k];
    }
    for (int o = 16; o > 0; o >>= 1) acc += __shfl_down_sync(0xffffffffu, acc, o);
    if (l == 0) out[row] = acc + bout[0];
}

// ---------------- launch ---------------------------------------------------
extern "C" void kernel_launch(void* const* d_in, const int* in_sizes, int n_in,
                              void* d_out, int out_size) {
    const float* pts    = (const float*)d_in[0];
    const float* rgb    = (const float*)d_in[1];
    const float* qc     = (const float*)d_in[2];
    const float* enc_W1 = (const float*)d_in[3];
    const float* enc_b1 = (const float*)d_in[4];
    const float* enc_W2 = (const float*)d_in[5];
    const float* enc_b2 = (const float*)d_in[6];
    const float* fc_p_W = (const float*)d_in[7];
    const float* fc_p_b = (const float*)d_in[8];
    const float* Wg0 = (const float*)d_in[9];
    const float* bg0 = (const float*)d_in[10];
    const float* Wb0 = (const float*)d_in[11];
    const float* bb0 = (const float*)d_in[12];
    const float* W0  = (const float*)d_in[13];
    const float* b0  = (const float*)d_in[14];
    const float* Wg1 = (const float*)d_in[15];
    const float* bg1 = (const float*)d_in[16];
    const float* Wb1 = (const float*)d_in[17];
    const float* bb1 = (const float*)d_in[18];
    const float* W1  = (const float*)d_in[19];
    const float* b1  = (const float*)d_in[20];
    const float* bnWg = (const float*)d_in[21];
    const float* bnbg = (const float*)d_in[22];
    const float* bnWb = (const float*)d_in[23];
    const float* bnbb = (const float*)d_in[24];
    const float* foW  = (const float*)d_in[25];
    const float* fob  = (const float*)d_in[26];
    float* out = (float*)d_out;

    cudaFuncSetAttribute(enc2_mma_kernel, cudaFuncAttributeMaxDynamicSharedMemorySize, E2_SMEM);
    cudaFuncSetAttribute(dec_mma_kernel<0>, cudaFuncAttributeMaxDynamicSharedMemorySize, D_SMEM);
    cudaFuncSetAttribute(dec_mma_kernel<1>, cudaFuncAttributeMaxDynamicSharedMemorySize, D_SMEM);

    zero_kernel<<<BB, 1024>>>();
    p99_kernel<<<BB, 1024>>>(pts);
    compact_kernel<<<M_ENC / 1024, 1024>>>(pts);
    {
        dim3 g(32, 32);
        w2conv_kernel<<<g, 256>>>(enc_W2);
    }
    {
        dim3 g(8, 8, 10);
        wdec_kernel<<<g, 256>>>(W0, W1);
    }
    {
        dim3 g(CW / 256, M_ENC / 128);
        enc2_mma_kernel<<<g, 256, E2_SMEM>>>(pts, rgb, enc_W1, enc_b1, enc_b2);
    }
    {
        dim3 g(BB, 11);
        gb_kernel<<<g, 1024>>>(Wg0, bg0, Wb0, bb0, Wg1, bg1, Wb1, bb1,
                               bnWg, bnbg, bnWb, bnbb);
    }
    fcp_kernel<<<256, 256>>>(qc, fc_p_W, fc_p_b);
    for (int i = 0; i < NBLK; i++) {
        dec_mma_kernel<0><<<128, 256, D_SMEM>>>(0, 2 * i, 2 * i, b0 + (size_t)i * DW);
        dec_mma_kernel<1><<<128, 256, D_SMEM>>>(1, 2 * i + 1, 2 * i + 1, b1 + (size_t)i * DW);
    }
    stats_final_kernel<<<1, 256>>>();
    head_kernel<<<M_DEC / 8, 256>>>(foW, fob, out);
}

// round 6
// speedup vs baseline: 1.1815x; 1.1815x over previous
#include <cuda_runtime.h>
#include <cuda_bf16.h>
#include <cuda_fp16.h>
#include <math.h>
#include <stdint.h>

#define BB   8
#define NPTS 8192
#define TT   2048
#define CW   1024
#define DW   256
#define NBLK 5
#define M_ENC (BB*NPTS)   /* 65536 */
#define M_DEC (BB*TT)     /* 16384 */

// ---------------- scratch (device globals; no allocation allowed) ----------
__device__ __half        g_w2hi[(size_t)CW * CW];   // [n][k] transposed, fp16 split
__device__ __half        g_w2lo[(size_t)CW * CW];
__device__ __nv_bfloat16 g_wdhi[10 * DW * DW];      // decoder weights [layer][n][k]
__device__ __nv_bfloat16 g_wdlo[10 * DW * DW];
__device__ int           g_sidx[M_ENC];
__device__ int           g_nv[BB];
__device__ int           g_cnt[BB];
__device__ float         g_p99[BB];
__device__ float         g_c[BB * CW];
__device__ float         g_net[M_DEC * DW];
__device__ float         g_t1[M_DEC * DW];
__device__ float         g_gamma[11 * BB * DW];
__device__ float         g_beta[11 * BB * DW];
__device__ float         g_psum[256 * DW];
__device__ float         g_psq[256 * DW];
__device__ float         g_mean[DW];
__device__ float         g_rstd[DW];

// ---------------- PTX helpers (all baseline sm_80+ features) ---------------
__device__ __forceinline__ uint32_t smem_u32(const void* p) {
    uint32_t a;
    asm("{ .reg .u64 t; cvta.to.shared.u64 t, %1; cvt.u32.u64 %0, t; }" : "=r"(a) : "l"(p));
    return a;
}
__device__ __forceinline__ void cp16(uint32_t dst, const void* src) {
    asm volatile("cp.async.cg.shared.global [%0], [%1], 16;"
                 :: "r"(dst), "l"(__cvta_generic_to_global(src)) : "memory");
}
#define CP_COMMIT() asm volatile("cp.async.commit_group;" ::: "memory")
template <int N>
__device__ __forceinline__ void cp_wait() {
    asm volatile("cp.async.wait_group %0;" :: "n"(N) : "memory");
}
__device__ __forceinline__ void ldsm4(uint32_t (&r)[4], uint32_t addr) {
    asm volatile("ldmatrix.sync.aligned.m8n8.x4.shared.b16 {%0,%1,%2,%3}, [%4];"
                 : "=r"(r[0]), "=r"(r[1]), "=r"(r[2]), "=r"(r[3]) : "r"(addr));
}
__device__ __forceinline__ void mma16816(float (&d)[4], const uint32_t (&a)[4],
                                         uint32_t b0, uint32_t b1) {
    asm volatile("mma.sync.aligned.m16n8k16.row.col.f32.bf16.bf16.f32 "
                 "{%0,%1,%2,%3}, {%4,%5,%6,%7}, {%8,%9}, {%0,%1,%2,%3};"
                 : "+f"(d[0]), "+f"(d[1]), "+f"(d[2]), "+f"(d[3])
                 : "r"(a[0]), "r"(a[1]), "r"(a[2]), "r"(a[3]), "r"(b0), "r"(b1));
}
__device__ __forceinline__ void mma16816h(float (&d)[4], const uint32_t (&a)[4],
                                          uint32_t b0, uint32_t b1) {
    asm volatile("mma.sync.aligned.m16n8k16.row.col.f32.f16.f16.f32 "
                 "{%0,%1,%2,%3}, {%4,%5,%6,%7}, {%8,%9}, {%0,%1,%2,%3};"
                 : "+f"(d[0]), "+f"(d[1]), "+f"(d[2]), "+f"(d[3])
                 : "r"(a[0]), "r"(a[1]), "r"(a[2]), "r"(a[3]), "r"(b0), "r"(b1));
}

// ---------------- small reduce helper --------------------------------------
__device__ __forceinline__ int blockReduceSumI(int v, int* sred) {
    for (int o = 16; o > 0; o >>= 1) v += __shfl_down_sync(0xffffffffu, v, o);
    int w = threadIdx.x >> 5;
    if ((threadIdx.x & 31) == 0) sred[w] = v;
    __syncthreads();
    if (threadIdx.x < 32) {
        int t = (threadIdx.x < (int)(blockDim.x >> 5)) ? sred[threadIdx.x] : 0;
        for (int o = 16; o > 0; o >>= 1) t += __shfl_down_sync(0xffffffffu, t, o);
        if (threadIdx.x == 0) sred[0] = t;
    }
    __syncthreads();
    int r = sred[0];
    __syncthreads();
    return r;
}

// ---------------- kernel: zero pooled code + counters ----------------------
__global__ void zero_kernel() {
    g_c[blockIdx.x * 1024 + threadIdx.x] = 0.0f;
    if (blockIdx.x == 0 && threadIdx.x < BB) g_cnt[threadIdx.x] = 0;
}

// ---------------- kernel: per-batch 99th percentile (exact kthvalue) -------
__global__ __launch_bounds__(1024) void p99_kernel(const float* __restrict__ pts) {
    __shared__ unsigned s_bits[NPTS];
    __shared__ int sred[33];
    const int b = blockIdx.x, tid = threadIdx.x;
    const float* p = pts + (size_t)b * NPTS * 3;
    int nv = 0;
    for (int i = tid; i < NPTS; i += 1024) {
        float x = p[3 * i], y = p[3 * i + 1], z = p[3 * i + 2];
        bool valid = x > -50.0f;
        float nr = valid ? sqrtf(x * x + y * y + z * z) : __int_as_float(0x7F800000);
        s_bits[i] = __float_as_uint(nr);
        nv += valid ? 1 : 0;
    }
    int total = blockReduceSumI(nv, sred);
    __shared__ int s_k;
    if (tid == 0) {
        s_k = 1 + (int)rintf(0.99f * (float)(total - 1));
        g_nv[b] = total;
    }
    __syncthreads();
    const int k = s_k;
    unsigned lo = 0u, hi = 0x7F800000u;
    while (lo < hi) {
        unsigned mid = (lo + hi) >> 1;
        int c = 0;
        for (int i = tid; i < NPTS; i += 1024) c += (s_bits[i] <= mid) ? 1 : 0;
        c = blockReduceSumI(c, sred);
        if (c >= k) hi = mid; else lo = mid + 1;
    }
    if (tid == 0) g_p99[b] = __uint_as_float(lo);
}

// ---------------- kernel: valid-point compaction ---------------------------
__global__ __launch_bounds__(1024) void compact_kernel(const float* __restrict__ pts) {
    int i = blockIdx.x * 1024 + threadIdx.x;
    if (pts[(size_t)i * 3] > -50.0f) {
        int b = i >> 13;
        int dst = atomicAdd(&g_cnt[b], 1);
        g_sidx[(b << 13) + dst] = i;
    }
}

// ---------------- kernel: W2 transpose + fp16 hi/lo split ------------------
__global__ __launch_bounds__(256) void w2conv_kernel(const float* __restrict__ W2) {
    __shared__ float t[32][33];
    const int bx = blockIdx.x, by = blockIdx.y;
    const int x = threadIdx.x & 31, y0 = threadIdx.x >> 5;
#pragma unroll
    for (int dy = 0; dy < 32; dy += 8)
        t[y0 + dy][x] = W2[(size_t)(by * 32 + y0 + dy) * CW + bx * 32 + x];
    __syncthreads();
#pragma unroll
    for (int dy = 0; dy < 32; dy += 8) {
        float v = t[x][y0 + dy];
        __half hi = __float2half(v);
        __half lo = __float2half(v - __half2float(hi));
        size_t o = (size_t)(bx * 32 + y0 + dy) * CW + by * 32 + x;
        g_w2hi[o] = hi;
        g_w2lo[o] = lo;
    }
}

// ---------------- kernel: decoder weights transpose + bf16 split -----------
__global__ __launch_bounds__(256) void wdec_kernel(const float* __restrict__ W0,
                                                   const float* __restrict__ W1) {
    __shared__ float t[32][33];
    const int bx = blockIdx.x, by = blockIdx.y, z = blockIdx.z;
    const float* src = ((z & 1) ? W1 : W0) + (size_t)(z >> 1) * DW * DW;
    const int x = threadIdx.x & 31, y0 = threadIdx.x >> 5;
#pragma unroll
    for (int dy = 0; dy < 32; dy += 8)
        t[y0 + dy][x] = src[(size_t)(by * 32 + y0 + dy) * DW + bx * 32 + x];
    __syncthreads();
#pragma unroll
    for (int dy = 0; dy < 32; dy += 8) {
        float v = t[x][y0 + dy];
        __nv_bfloat16 hi = __float2bfloat16(v);
        __nv_bfloat16 lo = __float2bfloat16(v - __bfloat162float(hi));
        size_t o = (size_t)z * DW * DW + (size_t)(bx * 32 + y0 + dy) * DW + by * 32 + x;
        g_wdhi[o] = hi;
        g_wdlo[o] = lo;
    }
}

// ---------------- kernel: fused enc1+enc2 fp16 mma GEMM + maxpool ----------
// CTA tile 128M x 256N, K-stage 32. A = single fp16 plane (computed in-kernel
// from 6-dim x), B = fp16 hi/lo split (2 mma passes).
// smem: B stages 3 x (Bhi 20480 + Blo 20480) | A bufs 2 x 10240
//       | W1 24576 | b1 4096 | x 3072
#define E2_BSTG   40960
#define E2_ABUF   122880
#define E2_W1     143360
#define E2_B1     167936
#define E2_X      172032
#define E2_SMEM   175104

__global__ __launch_bounds__(256, 1) void enc2_mma_kernel(const float* __restrict__ pts,
                                                          const float* __restrict__ rgb,
                                                          const float* __restrict__ W1g,
                                                          const float* __restrict__ b1g,
                                                          const float* __restrict__ b2) {
    extern __shared__ __align__(128) char sm[];
    __shared__ float sbias[256];
    const uint32_t smb = smem_u32(sm);
    const int tid = threadIdx.x;
    const int cb = blockIdx.x;          // 0..3  N-strip of 256
    const int rb = blockIdx.y;          // 0..511 M-tile of 128
    const int batch = rb >> 6;
    const int n_b = g_nv[batch];
    const int rib0 = (rb & 63) * 128;
    if (rib0 >= n_b) return;
    const int validRows = n_b - rib0;
    const int l = tid & 31, w = tid >> 5;
    const int warp_m = w >> 2, warp_n = w & 3;

    sbias[tid] = b2[cb * 256 + tid];

    // B cp.async mapping (8 chunks/thread/stage)
    const __half* gsrc[8];
    uint32_t soff[8];
#pragma unroll
    for (int q = 0; q < 8; q++) {
        int ch = tid + q * 256;
        int plane = ch >> 10, idx = ch & 1023;
        int row = idx >> 2, c = idx & 3;
        gsrc[q] = (plane ? g_w2lo : g_w2hi) + (size_t)(cb * 256 + row) * CW + c * 8;
        soff[q] = plane * 20480 + row * 80 + c * 16;
    }
#define E2_ISSUE(it) do { \
        uint32_t sb_ = smb + ((it) % 3) * E2_BSTG; \
        _Pragma("unroll") \
        for (int q = 0; q < 8; q++) cp16(sb_ + soff[q], gsrc[q] + (it) * 32); \
        CP_COMMIT(); \
    } while (0)

    // prologue group0: W1 + b1 + B(0); group1: B(1)
#pragma unroll
    for (int q = 0; q < 6; q++) {
        int ch = tid + q * 256;
        cp16(smb + E2_W1 + ch * 16, W1g + ch * 4);
    }
    cp16(smb + E2_B1 + tid * 16, b1g + tid * 4);
    E2_ISSUE(0);
    E2_ISSUE(1);

    // x gather (plain loads)
    if (tid < 128) {
        int idx = rib0 + tid;
        if (idx >= n_b) idx = n_b - 1;
        int src = g_sidx[(batch << 13) + idx];
        float p99v = g_p99[batch];
        float* sx = (float*)(sm + E2_X) + tid * 6;
        sx[0] = pts[(size_t)src * 3 + 0] / p99v;
        sx[1] = pts[(size_t)src * 3 + 1] / p99v;
        sx[2] = pts[(size_t)src * 3 + 2] / p99v;
        sx[3] = rgb[(size_t)src * 3 + 0];
        sx[4] = rgb[(size_t)src * 3 + 1];
        sx[5] = rgb[(size_t)src * 3 + 2];
    }
    cp_wait<1>();                       // W1, b1, B(0) landed
    __syncthreads();                    // + x visible

    // --- compute A stage s (relu(x@W1+b1) -> single fp16 plane) ------------
    const int arow = tid >> 1, ahalf = tid & 1;
    float xr[6];
    {
        const float* sx = (const float*)(sm + E2_X) + arow * 6;
#pragma unroll
        for (int j = 0; j < 6; j++) xr[j] = sx[j];
    }
    const float* sW1 = (const float*)(sm + E2_W1);
    const float* sb1 = (const float*)(sm + E2_B1);
#define E2_COMPUTE_A(s) do { \
        int k0 = (s) * 32 + ahalf * 16; \
        uint32_t hh[8]; \
        _Pragma("unroll") \
        for (int c2 = 0; c2 < 8; c2++) { \
            float z0 = sb1[k0 + 2 * c2], z1 = sb1[k0 + 2 * c2 + 1]; \
            _Pragma("unroll") \
            for (int j = 0; j < 6; j++) { \
                z0 += xr[j] * sW1[j * CW + k0 + 2 * c2]; \
                z1 += xr[j] * sW1[j * CW + k0 + 2 * c2 + 1]; \
            } \
            __half h0 = __float2half(fmaxf(z0, 0.f)); \
            __half h1 = __float2half(fmaxf(z1, 0.f)); \
            hh[c2] = (uint32_t)*(uint16_t*)&h0 | ((uint32_t)*(uint16_t*)&h1 << 16); \
        } \
        char* dh = sm + E2_ABUF + ((s) & 1) * 10240 + arow * 80 + ahalf * 32; \
        ((uint4*)dh)[0] = make_uint4(hh[0], hh[1], hh[2], hh[3]); \
        ((uint4*)dh)[1] = make_uint4(hh[4], hh[5], hh[6], hh[7]); \
    } while (0)

    E2_COMPUTE_A(0);

    const uint32_t a_lane = (uint32_t)(warp_m * 64 + (l & 15)) * 80 + ((l >> 4) & 1) * 16;
    const uint32_t b_lane = (uint32_t)(warp_n * 64 + ((l >> 4) & 1) * 8 + (l & 7)) * 80
                          + ((l >> 3) & 1) * 16;

    float acc[4][8][4];
#pragma unroll
    for (int m = 0; m < 4; m++)
#pragma unroll
        for (int n = 0; n < 8; n++)
#pragma unroll
            for (int j = 0; j < 4; j++) acc[m][n][j] = 0.0f;

    const int NIT = CW / 32;            // 32
#pragma unroll 1
    for (int it = 0; it < NIT; it++) {
        if (it + 1 < NIT) cp_wait<1>(); else cp_wait<0>();
        __syncthreads();
        if (it + 2 < NIT) E2_ISSUE(it + 2);
        if (it + 1 < NIT) E2_COMPUTE_A(it + 1);

        const uint32_t ba = smb + E2_ABUF + (it & 1) * 10240;
        const uint32_t bb_ = smb + (it % 3) * E2_BSTG;
#pragma unroll
        for (int k16 = 0; k16 < 2; k16++) {
            const uint32_t kb = k16 * 32;
            uint32_t Ah[4][4], Bh[4][4], Bl[4][4];
#pragma unroll
            for (int m = 0; m < 4; m++)
                ldsm4(Ah[m], ba + a_lane + m * (16 * 80) + kb);
#pragma unroll
            for (int p = 0; p < 4; p++)
                ldsm4(Bh[p], bb_ + b_lane + p * (16 * 80) + kb);
#pragma unroll
            for (int p = 0; p < 4; p++)
                ldsm4(Bl[p], bb_ + 20480 + b_lane + p * (16 * 80) + kb);
#pragma unroll
            for (int m = 0; m < 4; m++)
#pragma unroll
                for (int p = 0; p < 4; p++) {
                    mma16816h(acc[m][2 * p],     Ah[m], Bh[p][0], Bh[p][1]);
                    mma16816h(acc[m][2 * p + 1], Ah[m], Bh[p][2], Bh[p][3]);
                }
#pragma unroll
            for (int m = 0; m < 4; m++)
#pragma unroll
                for (int p = 0; p < 4; p++) {
                    mma16816h(acc[m][2 * p],     Ah[m], Bl[p][0], Bl[p][1]);
                    mma16816h(acc[m][2 * p + 1], Ah[m], Bl[p][2], Bl[p][3]);
                }
        }
    }

    // --- epilogue: bias + relu + masked column max -> atomicMax ------------
    const int groupID = l >> 2, tig = l & 3;
    unsigned mA[4], mB[4];
#pragma unroll
    for (int m = 0; m < 4; m++) {
        mA[m] = (warp_m * 64 + m * 16 + groupID)     < validRows;
        mB[m] = (warp_m * 64 + m * 16 + groupID + 8) < validRows;
    }
    const float NEGINF = __int_as_float(0xFF800000);
#pragma unroll
    for (int nt = 0; nt < 8; nt++) {
#pragma unroll
        for (int p = 0; p < 2; p++) {
            float bias = sbias[warp_n * 64 + nt * 8 + tig * 2 + p];
            float cm = NEGINF;
#pragma unroll
            for (int m = 0; m < 4; m++) {
                if (mA[m]) cm = fmaxf(cm, fmaxf(acc[m][nt][p] + bias, 0.0f));
                if (mB[m]) cm = fmaxf(cm, fmaxf(acc[m][nt][2 + p] + bias, 0.0f));
            }
            cm = fmaxf(cm, __shfl_xor_sync(0xffffffffu, cm, 16));
            cm = fmaxf(cm, __shfl_xor_sync(0xffffffffu, cm, 8));
            cm = fmaxf(cm, __shfl_xor_sync(0xffffffffu, cm, 4));
            if (l < 4)
                atomicMax((int*)&g_c[batch * CW + cb * 256 + warp_n * 64 + nt * 8 + l * 2 + p],
                          __float_as_int(cm));
        }
    }
#undef E2_ISSUE
#undef E2_COMPUTE_A
}

// ---------------- kernel: all 22 CBN gamma/beta projections ----------------
__global__ __launch_bounds__(1024) void gb_kernel(
    const float* __restrict__ Wg0, const float* __restrict__ bg0,
    const float* __restrict__ Wb0, const float* __restrict__ bb0,
    const float* __restrict__ Wg1, const float* __restrict__ bg1,
    const float* __restrict__ Wb1, const float* __restrict__ bb1,
    const float* __restrict__ bnWg, const float* __restrict__ bnbg,
    const float* __restrict__ bnWb, const float* __restrict__ bnbb) {
    __shared__ float sc[CW];
    __shared__ float rg[4][DW], rb[4][DW];
    const int b = blockIdx.x, id = blockIdx.y;
    const int tid = threadIdx.x;
    for (int i = tid; i < CW; i += 1024) sc[i] = g_c[b * CW + i];
    const float *Wg, *Wb, *bg, *bbp;
    if (id < 10) {
        int i = id >> 1;
        if (!(id & 1)) { Wg = Wg0 + (size_t)i * CW * DW; bg = bg0 + i * DW;
                         Wb = Wb0 + (size_t)i * CW * DW; bbp = bb0 + i * DW; }
        else           { Wg = Wg1 + (size_t)i * CW * DW; bg = bg1 + i * DW;
                         Wb = Wb1 + (size_t)i * CW * DW; bbp = bb1 + i * DW; }
    } else { Wg = bnWg; bg = bnbg; Wb = bnWb; bbp = bnbb; }
    __syncthreads();
    const int col = tid & 255, kc = tid >> 8;
    float sg = 0.f, sb = 0.f;
    for (int k = kc * 256; k < (kc + 1) * 256; k++) {
        float cv = sc[k];
        sg += cv * Wg[(size_t)k * DW + col];
        sb += cv * Wb[(size_t)k * DW + col];
    }
    rg[kc][col] = sg; rb[kc][col] = sb;
    __syncthreads();
    if (tid < 256) {
        float ga = bg[col], be = bbp[col];
#pragma unroll
        for (int t = 0; t < 4; t++) { ga += rg[t][col]; be += rb[t][col]; }
        g_gamma[(id * BB + b) * DW + col] = ga;
        g_beta [(id * BB + b) * DW + col] = be;
    }
}

// ---------------- kernel: fc_p (3 -> 256) + fused stats (256 slots) --------
__global__ __launch_bounds__(256) void fcp_kernel(const float* __restrict__ qc,
                                                  const float* __restrict__ W,
                                                  const float* __restrict__ bias) {
    __shared__ float sW[3 * DW];
    __shared__ float sx[64][3];
    const int tid = threadIdx.x;
    const int r0 = blockIdx.x * 64;
    const int b = r0 >> 11;
    for (int i = tid; i < 3 * DW; i += 256) sW[i] = W[i];
    if (tid < 192) {
        int r = tid / 3, cc = tid % 3;
        sx[r][cc] = qc[(size_t)(r0 + r) * 3 + cc] / g_p99[b];
    }
    __syncthreads();
    const int col = tid;
    const float bv = bias[col];
    float s = 0.f, q = 0.f;
    for (int r = 0; r < 64; r++) {
        float o = bv;
#pragma unroll
        for (int k = 0; k < 3; k++) o += sx[r][k] * sW[k * DW + col];
        g_net[(size_t)(r0 + r) * DW + col] = o;
        s += o; q += o * o;
    }
    g_psum[(size_t)blockIdx.x * DW + col] = s;
    g_psq [(size_t)blockIdx.x * DW + col] = q;
}

// ---------------- kernel: BN stats finalize (pre-head only) ----------------
__global__ __launch_bounds__(256) void stats_final_kernel() {
    const int col = threadIdx.x;
    float s = 0.f, q = 0.f;
#pragma unroll 8
    for (int t = 0; t < 256; t++) {
        s += g_psum[(size_t)t * DW + col];
        q += g_psq [(size_t)t * DW + col];
    }
    float mean = s * (1.0f / 16384.0f);
    float var = q * (1.0f / 16384.0f) - mean * mean;
    if (var < 0.f) var = 0.f;
    g_mean[col] = mean;
    g_rstd[col] = rsqrtf(var + 1e-5f);
}

// ---------------- kernel: decoder mma GEMM, fused stats+CBN+ReLU -----------
#define D_AF32  0
#define D_AHI   18432
#define D_ALO   28672
#define D_BHI   38912
#define D_BLO   59392
#define D_STAGE 79872
#define D_SMEM  (2 * D_STAGE)

template <int ADD>
__global__ __launch_bounds__(256, 1) void dec_mma_kernel(int xsel, int id, int layer,
                                                         const float* __restrict__ bias) {
    extern __shared__ __align__(128) char sm[];
    __shared__ float s_sc[DW], s_sh[DW], s_bias[DW];
    const uint32_t smb = smem_u32(sm);
    const int tid = threadIdx.x;
    const int rb = blockIdx.x;          // 0..127 M-tiles
    const int batch = rb >> 4;
    const int l = tid & 31, w = tid >> 5;
    const int warp_m = w >> 2, warp_n = w & 3;
    const float* X = xsel ? g_t1 : g_net;
    float* out = ADD ? g_net : g_t1;

    const float* asrc[4]; uint32_t aoff[4];
#pragma unroll
    for (int q = 0; q < 4; q++) {
        int ch = tid + q * 256;
        int row = ch >> 3, c = ch & 7;
        asrc[q] = X + (size_t)(rb * 128 + row) * DW + c * 4;
        aoff[q] = D_AF32 + row * 144 + c * 16;
    }
    const __nv_bfloat16* bsrc[8]; uint32_t boff[8];
#pragma unroll
    for (int q = 0; q < 8; q++) {
        int ch = tid + q * 256;
        int plane = ch >> 10, idx = ch & 1023;
        int row = idx >> 2, c = idx & 3;
        bsrc[q] = (plane ? g_wdlo : g_wdhi) + (size_t)layer * DW * DW + row * DW + c * 8;
        boff[q] = D_BHI + plane * 20480 + row * 80 + c * 16;
    }
#define D_ISSUE(it) do { \
        uint32_t sb_ = smb + ((it) & 1) * D_STAGE; \
        _Pragma("unroll") for (int q = 0; q < 4; q++) cp16(sb_ + aoff[q], asrc[q] + (it) * 32); \
        _Pragma("unroll") for (int q = 0; q < 8; q++) cp16(sb_ + boff[q], bsrc[q] + (it) * 32); \
        CP_COMMIT(); \
    } while (0)

    D_ISSUE(0);
    D_ISSUE(1);

    // fused BN stats (overlaps the cp.async above)
    {
        float s = 0.f, q = 0.f;
#pragma unroll 8
        for (int t = 0; t < 256; t++) {
            s += g_psum[(size_t)t * DW + tid];
            q += g_psq [(size_t)t * DW + tid];
        }
        float mean = s * (1.0f / 16384.0f);
        float var = q * (1.0f / 16384.0f) - mean * mean;
        if (var < 0.f) var = 0.f;
        float rstd = rsqrtf(var + 1e-5f);
        float sc = g_gamma[(id * BB + batch) * DW + tid] * rstd;
        s_sc[tid] = sc;
        s_sh[tid] = g_beta[(id * BB + batch) * DW + tid] - mean * sc;
        s_bias[tid] = bias[tid];
    }

    const uint32_t a_lane = (uint32_t)(warp_m * 64 + (l & 15)) * 80 + ((l >> 4) & 1) * 16;
    const uint32_t b_lane = (uint32_t)(warp_n * 64 + ((l >> 4) & 1) * 8 + (l & 7)) * 80
                          + ((l >> 3) & 1) * 16;

    float acc[4][8][4];
#pragma unroll
    for (int m = 0; m < 4; m++)
#pragma unroll
        for (int n = 0; n < 8; n++)
#pragma unroll
            for (int j = 0; j < 4; j++) acc[m][n][j] = 0.0f;

    const int cmr = tid >> 1, ckq = (tid & 1) * 16;
    const int NIT = DW / 32;            // 8
#pragma unroll 1
    for (int it = 0; it < NIT; it++) {
        if (it + 1 < NIT) cp_wait<1>(); else cp_wait<0>();
        __syncthreads();
        const int buf = it & 1;
        {
            const char* afp = sm + buf * D_STAGE + D_AF32 + cmr * 144 + ckq * 4;
            float4 f0 = *(const float4*)(afp);
            float4 f1 = *(const float4*)(afp + 16);
            float4 f2 = *(const float4*)(afp + 32);
            float4 f3 = *(const float4*)(afp + 48);
            float f[16] = {f0.x, f0.y, f0.z, f0.w, f1.x, f1.y, f1.z, f1.w,
                           f2.x, f2.y, f2.z, f2.w, f3.x, f3.y, f3.z, f3.w};
            uint32_t hi[8], lo[8];
#pragma unroll
            for (int j = 0; j < 8; j++) {
                int k0 = it * 32 + ckq + 2 * j;
                float va = fmaxf(fmaf(f[2 * j],     s_sc[k0],     s_sh[k0]),     0.f);
                float vb = fmaxf(fmaf(f[2 * j + 1], s_sc[k0 + 1], s_sh[k0 + 1]), 0.f);
                __nv_bfloat16 ha = __float2bfloat16(va), hb = __float2bfloat16(vb);
                __nv_bfloat16 la = __float2bfloat16(va - __bfloat162float(ha));
                __nv_bfloat16 lb = __float2bfloat16(vb - __bfloat162float(hb));
                hi[j] = (uint32_t)*(uint16_t*)&ha | ((uint32_t)*(uint16_t*)&hb << 16);
                lo[j] = (uint32_t)*(uint16_t*)&la | ((uint32_t)*(uint16_t*)&lb << 16);
            }
            char* dh = sm + buf * D_STAGE + D_AHI + cmr * 80 + ckq * 2;
            ((uint4*)dh)[0] = make_uint4(hi[0], hi[1], hi[2], hi[3]);
            ((uint4*)dh)[1] = make_uint4(hi[4], hi[5], hi[6], hi[7]);
            char* dl = sm + buf * D_STAGE + D_ALO + cmr * 80 + ckq * 2;
            ((uint4*)dl)[0] = make_uint4(lo[0], lo[1], lo[2], lo[3]);
            ((uint4*)dl)[1] = make_uint4(lo[4], lo[5], lo[6], lo[7]);
        }
        __syncthreads();
        const uint32_t bs = smb + buf * D_STAGE;
#pragma unroll
        for (int k16 = 0; k16 < 2; k16++) {
            const uint32_t kb = k16 * 32;
            uint32_t Ah[4][4], Bh[4][4];
#pragma unroll
            for (int m = 0; m < 4; m++)
                ldsm4(Ah[m], bs + D_AHI + a_lane + m * (16 * 80) + kb);
#pragma unroll
            for (int p = 0; p < 4; p++)
                ldsm4(Bh[p], bs + D_BHI + b_lane + p * (16 * 80) + kb);
#pragma unroll
            for (int m = 0; m < 4; m++)
#pragma unroll
                for (int p = 0; p < 4; p++) {
                    mma16816(acc[m][2 * p],     Ah[m], Bh[p][0], Bh[p][1]);
                    mma16816(acc[m][2 * p + 1], Ah[m], Bh[p][2], Bh[p][3]);
                }
            uint32_t Bl[4][4];
#pragma unroll
            for (int p = 0; p < 4; p++)
                ldsm4(Bl[p], bs + D_BLO + b_lane + p * (16 * 80) + kb);
#pragma unroll
            for (int m = 0; m < 4; m++)
#pragma unroll
                for (int p = 0; p < 4; p++) {
                    mma16816(acc[m][2 * p],     Ah[m], Bl[p][0], Bl[p][1]);
                    mma16816(acc[m][2 * p + 1], Ah[m], Bl[p][2], Bl[p][3]);
                }
            uint32_t Al[4][4];
#pragma unroll
            for (int m = 0; m < 4; m++)
                ldsm4(Al[m], bs + D_ALO + a_lane + m * (16 * 80) + kb);
#pragma unroll
            for (int m = 0; m < 4; m++)
#pragma unroll
                for (int p = 0; p < 4; p++) {
                    mma16816(acc[m][2 * p],     Al[m], Bh[p][0], Bh[p][1]);
                    mma16816(acc[m][2 * p + 1], Al[m], Bh[p][2], Bh[p][3]);
                }
        }
        __syncthreads();
        if (it + 2 < NIT) D_ISSUE(it + 2);
    }
#undef D_ISSUE

    // --- epilogue: bias (+residual), store, fused column stats -------------
    const int groupID = l >> 2, tig = l & 3;
    const int slot = rb * 2 + warp_m;
#pragma unroll
    for (int nt = 0; nt < 8; nt++) {
        const int colbase = warp_n * 64 + nt * 8 + tig * 2;
        const float bv0 = s_bias[colbase], bv1 = s_bias[colbase + 1];
        float s0 = 0.f, s1 = 0.f, q0 = 0.f, q1 = 0.f;
#pragma unroll
        for (int m = 0; m < 4; m++) {
            int r = rb * 128 + warp_m * 64 + m * 16 + groupID;
            float v00 = acc[m][nt][0] + bv0, v01 = acc[m][nt][1] + bv1;
            float v10 = acc[m][nt][2] + bv0, v11 = acc[m][nt][3] + bv1;
            if (ADD) {
                float2 o0 = *(const float2*)&g_net[(size_t)r * DW + colbase];
                float2 o1 = *(const float2*)&g_net[(size_t)(r + 8) * DW + colbase];
                v00 += o0.x; v01 += o0.y; v10 += o1.x; v11 += o1.y;
            }
            *(float2*)&out[(size_t)r * DW + colbase]       = make_float2(v00, v01);
            *(float2*)&out[(size_t)(r + 8) * DW + colbase] = make_float2(v10, v11);
            s0 += v00 + v10; s1 += v01 + v11;
            q0 += v00 * v00 + v10 * v10; q1 += v01 * v01 + v11 * v11;
        }
#pragma unroll
        for (int o = 16; o >= 4; o >>= 1) {
            s0 += __shfl_xor_sync(0xffffffffu, s0, o);
            s1 += __shfl_xor_sync(0xffffffffu, s1, o);
            q0 += __shfl_xor_sync(0xffffffffu, q0, o);
            q1 += __shfl_xor_sync(0xffffffffu, q1, o);
        }
        if (l < 4) {
            g_psum[(size_t)slot * DW + colbase]     = s0;
            g_psum[(size_t)slot * DW + colbase + 1] = s1;
            g_psq [(size_t)slot * DW + colbase]     = q0;
            g_psq [(size_t)slot * DW + colbase + 1] = q1;
        }
    }
}

// ---------------- kernel: final head (CBN+ReLU then 256 -> 1) --------------
__global__ __launch_bounds__(256) void head_kernel(const float* __restrict__ Wout,
                                                   const float* __restrict__ bout,
                                                   float* __restrict__ out) {
    __shared__ float s_sc[DW], s_sh[DW], s_w[DW];
    const int tid = threadIdx.x;
    const int r0 = blockIdx.x * 8;
    const int batch = r0 >> 11;
    if (tid < DW) {
        float sc = g_gamma[(10 * BB + batch) * DW + tid] * g_rstd[tid];
        s_sc[tid] = sc;
        s_sh[tid] = g_beta[(10 * BB + batch) * DW + tid] - g_mean[tid] * sc;
        s_w[tid] = Wout[tid];
    }
    __syncthreads();
    const int w = tid >> 5, l = tid & 31;
    const int row = r0 + w;
    float acc = 0.f;
#pragma unroll
    for (int k = l; k < DW; k += 32) {
        float v = fmaxf(s_sc[k] * g_net[(size_t)row * DW + k] + s_sh[k], 0.f);
        acc += v * s_w[k];
    }
    for (int o = 16; o > 0; o >>= 1) acc += __shfl_down_sync(0xffffffffu, acc, o);
    if (l == 0) out[row] = acc + bout[0];
}

// ---------------- launch ---------------------------------------------------
extern "C" void kernel_launch(void* const* d_in, const int* in_sizes, int n_in,
                              void* d_out, int out_size) {
    const float* pts    = (const float*)d_in[0];
    const float* rgb    = (const float*)d_in[1];
    const float* qc     = (const float*)d_in[2];
    const float* enc_W1 = (const float*)d_in[3];
    const float* enc_b1 = (const float*)d_in[4];
    const float* enc_W2 = (const float*)d_in[5];
    const float* enc_b2 = (const float*)d_in[6];
    const float* fc_p_W = (const float*)d_in[7];
    const float* fc_p_b = (const float*)d_in[8];
    const float* Wg0 = (const float*)d_in[9];
    const float* bg0 = (const float*)d_in[10];
    const float* Wb0 = (const float*)d_in[11];
    const float* bb0 = (const float*)d_in[12];
    const float* W0  = (const float*)d_in[13];
    const float* b0  = (const float*)d_in[14];
    const float* Wg1 = (const float*)d_in[15];
    const float* bg1 = (const float*)d_in[16];
    const float* Wb1 = (const float*)d_in[17];
    const float* bb1 = (const float*)d_in[18];
    const float* W1  = (const float*)d_in[19];
    const float* b1  = (const float*)d_in[20];
    const float* bnWg = (const float*)d_in[21];
    const float* bnbg = (const float*)d_in[22];
    const float* bnWb = (const float*)d_in[23];
    const float* bnbb = (const float*)d_in[24];
    const float* foW  = (const float*)d_in[25];
    const float* fob  = (const float*)d_in[26];
    float* out = (float*)d_out;

    cudaFuncSetAttribute(enc2_mma_kernel, cudaFuncAttributeMaxDynamicSharedMemorySize, E2_SMEM);
    cudaFuncSetAttribute(dec_mma_kernel<0>, cudaFuncAttributeMaxDynamicSharedMemorySize, D_SMEM);
    cudaFuncSetAttribute(dec_mma_kernel<1>, cudaFuncAttributeMaxDynamicSharedMemorySize, D_SMEM);

    zero_kernel<<<BB, 1024>>>();
    p99_kernel<<<BB, 1024>>>(pts);
    compact_kernel<<<M_ENC / 1024, 1024>>>(pts);
    {
        dim3 g(32, 32);
        w2conv_kernel<<<g, 256>>>(enc_W2);
    }
    {
        dim3 g(8, 8, 10);
        wdec_kernel<<<g, 256>>>(W0, W1);
    }
    {
        dim3 g(CW / 256, M_ENC / 128);
        enc2_mma_kernel<<<g, 256, E2_SMEM>>>(pts, rgb, enc_W1, enc_b1, enc_b2);
    }
    {
        dim3 g(BB, 11);
        gb_kernel<<<g, 1024>>>(Wg0, bg0, Wb0, bb0, Wg1, bg1, Wb1, bb1,
                               bnWg, bnbg, bnWb, bnbb);
    }
    fcp_kernel<<<256, 256>>>(qc, fc_p_W, fc_p_b);
    for (int i = 0; i < NBLK; i++) {
        dec_mma_kernel<0><<<128, 256, D_SMEM>>>(0, 2 * i, 2 * i, b0 + (size_t)i * DW);
        dec_mma_kernel<1><<<128, 256, D_SMEM>>>(1, 2 * i + 1, 2 * i + 1, b1 + (size_t)i * DW);
    }
    stats_final_kernel<<<1, 256>>>();
    head_kernel<<<M_DEC / 8, 256>>>(foW, fob, out);
}